// round 2
// baseline (speedup 1.0000x reference)
#include <cuda_runtime.h>
#include <cstdint>

#define SLOPE 0.15f

static const int NN = 50000;   // nodes (fixed by problem)

// ---------------- device scratch (no runtime allocation allowed) -------------
__device__ float g_cntinv[NN];                 // 1/max(deg,1)
__device__ float g_agg  [NN * 256];            // segment-sum buffer (max dim 256)
__device__ float g_h1   [NN * 512];
__device__ float g_z2   [NN * 256];
__device__ float g_r2   [NN * 256];
__device__ float g_h2   [NN * 256];
__device__ float g_z3   [NN * 64];
__device__ float g_r3   [NN * 64];
__device__ float g_h3   [NN * 64];

// ---------------- small utility kernels --------------------------------------
__global__ void zero4_kernel(float* __restrict__ p, int n4) {
    int i = blockIdx.x * blockDim.x + threadIdx.x;
    if (i < n4) ((float4*)p)[i] = make_float4(0.f, 0.f, 0.f, 0.f);
}

__global__ void count_kernel(const int* __restrict__ dst, float* __restrict__ cnt, int ne) {
    int e = blockIdx.x * blockDim.x + threadIdx.x;
    if (e < ne) atomicAdd(&cnt[dst[e]], 1.0f);
}

__global__ void invert_kernel(float* __restrict__ c, int n) {
    int i = blockIdx.x * blockDim.x + threadIdx.x;
    if (i < n) c[i] = 1.0f / fmaxf(c[i], 1.0f);
}

// vectorized global reduction add (sm_90+)
__device__ __forceinline__ void red_add_v4(float* addr, float4 v) {
    asm volatile("red.global.add.v4.f32 [%0], {%1,%2,%3,%4};"
                 :: "l"(addr), "f"(v.x), "f"(v.y), "f"(v.z), "f"(v.w) : "memory");
}

// segment-sum: out[dst] += feat[src] over edges, d4 = dim/4
__global__ void agg_kernel(const float* __restrict__ feat, const int* __restrict__ src,
                           const int* __restrict__ dst, float* __restrict__ out,
                           int d4, int ne) {
    long long idx = (long long)blockIdx.x * blockDim.x + threadIdx.x;
    long long total = (long long)ne * d4;
    if (idx >= total) return;
    int e = (int)(idx / d4);
    int c = (int)(idx % d4);
    int s = src[e], d = dst[e];
    float4 v = *(const float4*)(feat + (size_t)s * d4 * 4 + c * 4);
    red_add_v4(out + (size_t)d * d4 * 4 + c * 4, v);
}

// h = leaky(agg*inv + bias + r)
__global__ void ew_kernel(const float* __restrict__ agg, const float* __restrict__ inv,
                          const float* __restrict__ r, const float* __restrict__ bias,
                          float* __restrict__ out, int d4, int n) {
    int idx = blockIdx.x * blockDim.x + threadIdx.x;
    if (idx >= n * d4) return;
    int row = idx / d4, c = idx % d4;
    float iv = inv[row];
    float4 a = ((const float4*)agg)[idx];
    float4 rr = ((const float4*)r)[idx];
    float4 b = ((const float4*)bias)[c];
    float4 o;
    o.x = fmaf(a.x, iv, b.x) + rr.x;
    o.y = fmaf(a.y, iv, b.y) + rr.y;
    o.z = fmaf(a.z, iv, b.z) + rr.z;
    o.w = fmaf(a.w, iv, b.w) + rr.w;
    o.x = o.x > 0.f ? o.x : SLOPE * o.x;
    o.y = o.y > 0.f ? o.y : SLOPE * o.y;
    o.z = o.z > 0.f ? o.z : SLOPE * o.z;
    o.w = o.w > 0.f ? o.w : SLOPE * o.w;
    ((float4*)out)[idx] = o;
}

// ---------------- f32x2 packed-FMA GEMM ---------------------------------------
// Tile 128(M) x 64(N) x 16(K), 256 threads, 8x4 per thread via 16 FFMA2/k.
// A smem tile stored K-major with DUPLICATED elements so LDS.128 yields two
// ready {a,a} f32x2 broadcast operands. B column pairs come free from LDS.128.

#define GBM 128
#define GBN 64
#define GBK 16
#define ASTRIDE 260   // words; 2*GBM + 4 pad; multiple of 4 for LDS.128 align

#define FLAG_CONCAT 1  // K split: A1 (scaled by cntinv) rows then A2; B1 rows then B2
#define FLAG_DUAL   2  // N split via gridDim.x: half 0 -> B1/C1, half 1 -> B2/C2
#define FLAG_BIAS   4
#define FLAG_LEAKY  8

__device__ __forceinline__ unsigned long long pk0() { return 0ull; }
__device__ __forceinline__ void fma2(unsigned long long &d, unsigned long long a, unsigned long long b) {
    asm("fma.rn.f32x2 %0, %1, %2, %0;" : "+l"(d) : "l"(a), "l"(b));
}
__device__ __forceinline__ float lo2(unsigned long long v) { return __uint_as_float((unsigned)v); }
__device__ __forceinline__ float hi2(unsigned long long v) { return __uint_as_float((unsigned)(v >> 32)); }

template<int FLAGS>
__global__ __launch_bounds__(256) void gemm2_kernel(
    const float* __restrict__ A1, const float* __restrict__ A2, int K1,
    const float* __restrict__ cntinv,
    const float* __restrict__ B1, const float* __restrict__ B2,
    float* __restrict__ C1, float* __restrict__ C2,
    const float* __restrict__ bias,
    int M, int N, int K)
{
    __shared__ float As[GBK * ASTRIDE];
    __shared__ float Bs[GBK * GBN];

    const int tid = threadIdx.x;
    const int bm = blockIdx.y * GBM;

    int bx = blockIdx.x;
    const int nbx = N / GBN;
    const float* Bsel = B1;
    float* Csel = C1;
    if (FLAGS & FLAG_DUAL) {
        if (bx >= nbx) { bx -= nbx; Bsel = B2; Csel = C2; }
    }
    const int bn = bx * GBN;

    // compute mapping
    const int tx = tid & 15;        // 4 cols at bn + tx*4
    const int ty = tid >> 4;        // 8 rows at bm + ty*8

    // A loader mapping (2 float4 per thread)
    int arow[2], ac4[2];
    bool aok[2];
    float asc[2];
    #pragma unroll
    for (int l = 0; l < 2; l++) {
        int lin = tid + 256 * l;
        arow[l] = lin >> 2;
        ac4[l]  = lin & 3;
        int gm = bm + arow[l];
        aok[l] = gm < M;
        asc[l] = 1.0f;
        if (FLAGS & FLAG_CONCAT) asc[l] = aok[l] ? cntinv[gm] : 1.0f;
    }
    // B loader mapping (1 float4 per thread)
    const int brow = tid >> 4;
    const int bc4  = (tid & 15) << 2;

    const int K2 = K - K1;

    unsigned long long acc[8][2];
    #pragma unroll
    for (int i = 0; i < 8; i++) { acc[i][0] = pk0(); acc[i][1] = pk0(); }

    float4 av[2], bv;

    // ---- tile loader into registers
    auto load_tile = [&](int k0) {
        #pragma unroll
        for (int l = 0; l < 2; l++) {
            int gm = bm + arow[l];
            const float* src;
            bool first = true;
            if (FLAGS & FLAG_CONCAT) {
                if (k0 < K1) { src = A1 + (size_t)gm * K1 + k0; }
                else         { src = A2 + (size_t)gm * K2 + (k0 - K1); first = false; }
            } else {
                src = A1 + (size_t)gm * K + k0;
            }
            float4 v = make_float4(0.f, 0.f, 0.f, 0.f);
            if (aok[l]) v = *(const float4*)(src + ac4[l] * 4);
            if ((FLAGS & FLAG_CONCAT) && first) {
                float s = asc[l];
                v.x *= s; v.y *= s; v.z *= s; v.w *= s;
            }
            av[l] = v;
        }
        const float* bsrc;
        if (FLAGS & FLAG_CONCAT) {
            if (k0 < K1) bsrc = B1 + (size_t)(k0 + brow) * N + bn + bc4;
            else         bsrc = B2 + (size_t)(k0 - K1 + brow) * N + bn + bc4;
        } else {
            bsrc = Bsel + (size_t)(k0 + brow) * N + bn + bc4;
        }
        bv = *(const float4*)bsrc;
    };

    auto store_tile = [&]() {
        #pragma unroll
        for (int l = 0; l < 2; l++) {
            int base_k = ac4[l] * 4;
            int m2 = 2 * arow[l];
            float vv[4] = {av[l].x, av[l].y, av[l].z, av[l].w};
            #pragma unroll
            for (int j = 0; j < 4; j++)
                *(float2*)&As[(base_k + j) * ASTRIDE + m2] = make_float2(vv[j], vv[j]);
        }
        *(float4*)&Bs[brow * GBN + bc4] = bv;
    };

    load_tile(0);
    store_tile();
    __syncthreads();

    const int ktiles = K / GBK;
    for (int t = 0; t < ktiles; t++) {
        if (t + 1 < ktiles) load_tile((t + 1) * GBK);
        #pragma unroll
        for (int k = 0; k < GBK; k++) {
            const ulonglong2* ap = (const ulonglong2*)&As[k * ASTRIDE + ty * 16];
            ulonglong2 u0 = ap[0];   // rows ty*8+0,1 as {a,a} pairs
            ulonglong2 u1 = ap[1];   // rows 2,3
            ulonglong2 u2 = ap[2];   // rows 4,5
            ulonglong2 u3 = ap[3];   // rows 6,7
            ulonglong2 b2v = *(const ulonglong2*)&Bs[k * GBN + tx * 4]; // {b0,b1},{b2,b3}
            fma2(acc[0][0], u0.x, b2v.x); fma2(acc[0][1], u0.x, b2v.y);
            fma2(acc[1][0], u0.y, b2v.x); fma2(acc[1][1], u0.y, b2v.y);
            fma2(acc[2][0], u1.x, b2v.x); fma2(acc[2][1], u1.x, b2v.y);
            fma2(acc[3][0], u1.y, b2v.x); fma2(acc[3][1], u1.y, b2v.y);
            fma2(acc[4][0], u2.x, b2v.x); fma2(acc[4][1], u2.x, b2v.y);
            fma2(acc[5][0], u2.y, b2v.x); fma2(acc[5][1], u2.y, b2v.y);
            fma2(acc[6][0], u3.x, b2v.x); fma2(acc[6][1], u3.x, b2v.y);
            fma2(acc[7][0], u3.y, b2v.x); fma2(acc[7][1], u3.y, b2v.y);
        }
        __syncthreads();
        if (t + 1 < ktiles) { store_tile(); __syncthreads(); }
    }

    // epilogue
    float4 bb = make_float4(0.f, 0.f, 0.f, 0.f);
    if (FLAGS & FLAG_BIAS) bb = *(const float4*)(bias + bn + tx * 4);
    #pragma unroll
    for (int i = 0; i < 8; i++) {
        int gm = bm + ty * 8 + i;
        if (gm >= M) continue;
        float4 v = make_float4(lo2(acc[i][0]), hi2(acc[i][0]), lo2(acc[i][1]), hi2(acc[i][1]));
        if (FLAGS & FLAG_BIAS) { v.x += bb.x; v.y += bb.y; v.z += bb.z; v.w += bb.w; }
        if (FLAGS & FLAG_LEAKY) {
            v.x = v.x > 0.f ? v.x : SLOPE * v.x;
            v.y = v.y > 0.f ? v.y : SLOPE * v.y;
            v.z = v.z > 0.f ? v.z : SLOPE * v.z;
            v.w = v.w > 0.f ? v.w : SLOPE * v.w;
        }
        *(float4*)(Csel + (size_t)gm * N + bn + tx * 4) = v;
    }
}

// ---------------- fused head: h3[64] -> Wp(32) -> leaky(Wf1(32)) -> Wf2(2) ----
__global__ __launch_bounds__(128) void head_kernel(
    const float* __restrict__ h3,
    const float* __restrict__ Wp, const float* __restrict__ bp,
    const float* __restrict__ Wf1, const float* __restrict__ bf1,
    const float* __restrict__ Wf2, const float* __restrict__ bf2,
    float* __restrict__ out, int n)
{
    __shared__ float sWp[64 * 32], sWf1[32 * 32], sWf2[64], sbp[32], sbf1[32], sbf2[2];
    for (int i = threadIdx.x; i < 64 * 32; i += blockDim.x) sWp[i] = Wp[i];
    for (int i = threadIdx.x; i < 32 * 32; i += blockDim.x) sWf1[i] = Wf1[i];
    for (int i = threadIdx.x; i < 64; i += blockDim.x) sWf2[i] = Wf2[i];
    if (threadIdx.x < 32) { sbp[threadIdx.x] = bp[threadIdx.x]; sbf1[threadIdx.x] = bf1[threadIdx.x]; }
    if (threadIdx.x < 2) sbf2[threadIdx.x] = bf2[threadIdx.x];
    __syncthreads();
    int nidx = blockIdx.x * blockDim.x + threadIdx.x;
    if (nidx >= n) return;

    float p[32];
#pragma unroll
    for (int j = 0; j < 32; j++) p[j] = sbp[j];
    const float* hx = h3 + (size_t)nidx * 64;
    for (int i = 0; i < 64; i++) {
        float xi = hx[i];
#pragma unroll
        for (int j = 0; j < 32; j++) p[j] = fmaf(xi, sWp[i * 32 + j], p[j]);
    }
    float q[32];
#pragma unroll
    for (int j = 0; j < 32; j++) q[j] = sbf1[j];
#pragma unroll
    for (int i = 0; i < 32; i++) {
#pragma unroll
        for (int j = 0; j < 32; j++) q[j] = fmaf(p[i], sWf1[i * 32 + j], q[j]);
    }
#pragma unroll
    for (int j = 0; j < 32; j++) q[j] = q[j] > 0.f ? q[j] : SLOPE * q[j];
    float o0 = sbf2[0], o1 = sbf2[1];
#pragma unroll
    for (int i = 0; i < 32; i++) { o0 = fmaf(q[i], sWf2[i * 2], o0); o1 = fmaf(q[i], sWf2[i * 2 + 1], o1); }
    out[(size_t)nidx * 2]     = o0;
    out[(size_t)nidx * 2 + 1] = o1;
}

// ---------------- launch ------------------------------------------------------
static inline int cdiv(long long a, int b) { return (int)((a + b - 1) / b); }

extern "C" void kernel_launch(void* const* d_in, const int* in_sizes, int n_in,
                              void* d_out, int out_size)
{
    const float* x   = (const float*)d_in[0];
    const int*   ei  = (const int*)d_in[1];
    // d_in[2] edge_attr, d_in[3] We, d_in[4] be: dead code in the reference
    const float* W1l = (const float*)d_in[5];
    const float* b1  = (const float*)d_in[6];
    const float* W1r = (const float*)d_in[7];
    const float* W2l = (const float*)d_in[8];
    const float* b2  = (const float*)d_in[9];
    const float* W2r = (const float*)d_in[10];
    const float* W3l = (const float*)d_in[11];
    const float* b3  = (const float*)d_in[12];
    const float* W3r = (const float*)d_in[13];
    const float* Wp  = (const float*)d_in[14];
    const float* bp  = (const float*)d_in[15];
    const float* Wf1 = (const float*)d_in[16];
    const float* bf1 = (const float*)d_in[17];
    const float* Wf2 = (const float*)d_in[18];
    const float* bf2 = (const float*)d_in[19];

    const int n  = in_sizes[0] / 128;   // 50000
    const int ne = in_sizes[1] / 2;     // 800000
    const int* src = ei;
    const int* dst = ei + ne;

    float *cntinv, *agg, *h1, *z2, *r2, *h2, *z3, *r3, *h3;
    cudaGetSymbolAddress((void**)&cntinv, g_cntinv);
    cudaGetSymbolAddress((void**)&agg,    g_agg);
    cudaGetSymbolAddress((void**)&h1,     g_h1);
    cudaGetSymbolAddress((void**)&z2,     g_z2);
    cudaGetSymbolAddress((void**)&r2,     g_r2);
    cudaGetSymbolAddress((void**)&h2,     g_h2);
    cudaGetSymbolAddress((void**)&z3,     g_z3);
    cudaGetSymbolAddress((void**)&r3,     g_r3);
    cudaGetSymbolAddress((void**)&h3,     g_h3);
    float* out = (float*)d_out;

    const int T = 256;
    const int gM = cdiv(n, GBM);   // 391

    // degree counts -> inverse
    zero4_kernel<<<cdiv(n / 4, T), T>>>(cntinv, n / 4);
    count_kernel<<<cdiv(ne, T), T>>>(dst, cntinv, ne);
    invert_kernel<<<cdiv(n, T), T>>>(cntinv, n);

    // ---- layer 1: aggregate x (dim 128); then one K-concat GEMM:
    //      h1 = leaky( [agg*cntinv | x] @ [W1l ; W1r] + b1 )
    zero4_kernel<<<cdiv((long long)n * 32, T), T>>>(agg, n * 32);
    agg_kernel<<<cdiv((long long)ne * 32, T), T>>>(x, src, dst, agg, 32, ne);
    gemm2_kernel<FLAG_CONCAT | FLAG_BIAS | FLAG_LEAKY><<<dim3(512 / GBN, gM), T>>>(
        agg, x, 128, cntinv, W1l, W1r, h1, nullptr, b1, n, 512, 256);

    // ---- layer 2: dual GEMM z2 = h1@W2l, r2 = h1@W2r; aggregate z2 (256d)
    gemm2_kernel<FLAG_DUAL><<<dim3(2 * 256 / GBN, gM), T>>>(
        h1, nullptr, 0, nullptr, W2l, W2r, z2, r2, nullptr, n, 256, 512);
    zero4_kernel<<<cdiv((long long)n * 64, T), T>>>(agg, n * 64);
    agg_kernel<<<cdiv((long long)ne * 64, T), T>>>(z2, src, dst, agg, 64, ne);
    ew_kernel<<<cdiv((long long)n * 64, T), T>>>(agg, cntinv, r2, b2, h2, 64, n);

    // ---- layer 3: dual GEMM z3/r3; aggregate z3 (64d)
    gemm2_kernel<FLAG_DUAL><<<dim3(2 * 64 / GBN, gM), T>>>(
        h2, nullptr, 0, nullptr, W3l, W3r, z3, r3, nullptr, n, 64, 256);
    zero4_kernel<<<cdiv((long long)n * 16, T), T>>>(agg, n * 16);
    agg_kernel<<<cdiv((long long)ne * 16, T), T>>>(z3, src, dst, agg, 16, ne);
    ew_kernel<<<cdiv((long long)n * 16, T), T>>>(agg, cntinv, r3, b3, h3, 16, n);

    // ---- fused head
    head_kernel<<<cdiv(n, 128), 128>>>(h3, Wp, bp, Wf1, bf1, Wf2, bf2, out, n);
}